// round 5
// baseline (speedup 1.0000x reference)
#include <cuda_runtime.h>
#include <cuda_bf16.h>
#include <cstdint>
#include <math.h>

// Problem constants
#define BB 2
#define SS 2048
#define DD 768
#define NH 12
#define DK 64
#define DV 64
#define GG 1
#define NIDX 6
#define SMID (SS - 2*GG)
#define MROWS (BB * SS)

// GEMM tiling
#define BM 128
#define BKK 32                    // bf16 K elems per stage
#define NCHK (DD / BKK)           // 24 k-iterations
#define LDT 40                    // padded row stride (elements): 80B
#define NSTG 4

// ---------------------------------------------------------------------------
// Scratch
// ---------------------------------------------------------------------------
__device__ float g_q[MROWS * DD];
__device__ float g_k[MROWS * DD];
__device__ float g_v[MROWS * DD];
__device__ float g_vsum[BB * NH * DV];

__device__ __nv_bfloat16 g_qh[MROWS * DD], g_ql[MROWS * DD];
__device__ __nv_bfloat16 g_kh[MROWS * DD], g_kl[MROWS * DD];
__device__ __nv_bfloat16 g_vh[MROWS * DD], g_vl[MROWS * DD];
__device__ __nv_bfloat16 g_ah[MROWS * DD], g_al[MROWS * DD];
__device__ __nv_bfloat16 g_wqh[DD * DD], g_wql[DD * DD];
__device__ __nv_bfloat16 g_wkh[DD * DD], g_wkl[DD * DD];
__device__ __nv_bfloat16 g_wvh[DD * DD], g_wvl[DD * DD];
__device__ __nv_bfloat16 g_woh[DD * DD], g_wol[DD * DD];

// ---------------------------------------------------------------------------
// PTX helpers (portable sm_80+ ISA)
// ---------------------------------------------------------------------------
__device__ __forceinline__ uint32_t smem_u32(const void* p) {
    uint32_t a;
    asm("{ .reg .u64 t; cvta.to.shared.u64 t, %1; cvt.u32.u64 %0, t; }"
        : "=r"(a) : "l"(p));
    return a;
}
__device__ __forceinline__ void cp_async16(uint32_t dst, const void* src) {
    asm volatile("cp.async.cg.shared.global [%0], [%1], 16;"
                 :: "r"(dst), "l"(src) : "memory");
}
__device__ __forceinline__ void cp_commit() {
    asm volatile("cp.async.commit_group;" ::: "memory");
}
template <int N>
__device__ __forceinline__ void cp_wait() {
    asm volatile("cp.async.wait_group %0;" :: "n"(N) : "memory");
}
__device__ __forceinline__ void ldm4(uint32_t* r, uint32_t addr) {
    asm volatile("ldmatrix.sync.aligned.m8n8.x4.shared.b16 {%0,%1,%2,%3}, [%4];"
                 : "=r"(r[0]), "=r"(r[1]), "=r"(r[2]), "=r"(r[3]) : "r"(addr));
}
__device__ __forceinline__ void mma16816(float* c, const uint32_t* a, const uint32_t* b) {
    asm volatile(
        "mma.sync.aligned.m16n8k16.row.col.f32.bf16.bf16.f32 "
        "{%0,%1,%2,%3}, {%4,%5,%6,%7}, {%8,%9}, {%0,%1,%2,%3};"
        : "+f"(c[0]), "+f"(c[1]), "+f"(c[2]), "+f"(c[3])
        : "r"(a[0]), "r"(a[1]), "r"(a[2]), "r"(a[3]), "r"(b[0]), "r"(b[1]));
}

struct GemmArgs {
    const __nv_bfloat16 *Ah, *Al, *Bh, *Bl;
    float* C;
};
struct Gemm3 { GemmArgs g[3]; };

// ---------------------------------------------------------------------------
// C[M,768] = Ah*Bh^T + Ah*Bl^T + Al*Bh^T  (bf16 split-fp32), B is [768,768]
// Template on BNT (CTA N-tile: 128 or 64). 8 warps, 2m x 4n layout.
// NSTG=4 cp.async stages, SINGLE __syncthreads per k-iter.
// ---------------------------------------------------------------------------
template <int BNT>
__global__ __launch_bounds__(256, 1) void gemm_mma(Gemm3 ga)
{
    constexpr int WNT = BNT / 4;                 // warp n-tile (32 or 16)
    constexpr int NJ = WNT / 8;                  // n8 tiles per warp (4 or 2)
    constexpr int TILEB_A = 128 * LDT * 2;       // 10240
    constexpr int TILEB_B = BNT * LDT * 2;
    constexpr int STAGEB = 2 * TILEB_A + 2 * TILEB_B;
    constexpr int NCHUNK = (2 * 128 + 2 * BNT) * 4;   // 16B chunks per stage
    constexpr int PER_THR = NCHUNK / 256;

    extern __shared__ char smem[];
    const GemmArgs& A = ga.g[blockIdx.z];
    const uint32_t sb = smem_u32(smem);
    const int tid = threadIdx.x;
    const int wid = tid >> 5;
    const int lane = tid & 31;
    const int bm = blockIdx.y * BM;
    const int bn = blockIdx.x * BNT;
    const int wm = (wid >> 2) * 64;
    const int wn = (wid & 3) * WNT;

    float acc[4][NJ][4];
    #pragma unroll
    for (int i = 0; i < 4; i++)
        #pragma unroll
        for (int j = 0; j < NJ; j++)
            #pragma unroll
            for (int e = 0; e < 4; e++) acc[i][j][e] = 0.0f;

    // chunk layout: [Ah(512) | Al(512) | Bh(BNT*4) | Bl(BNT*4)]
    auto issue = [&](int kt) {
        const int st = kt % NSTG;
        #pragma unroll
        for (int q8 = 0; q8 < PER_THR; q8++) {
            int q = tid + q8 * 256;
            const __nv_bfloat16* src;
            uint32_t dst;
            if (q < 1024) {
                int t = q >> 9;                  // 0=Ah 1=Al
                int r = (q >> 2) & 127;
                int c = q & 3;
                src = (t ? A.Al : A.Ah) + (size_t)(bm + r) * DD + kt * BKK + c * 8;
                dst = sb + st * STAGEB + t * TILEB_A + r * (LDT * 2) + c * 16;
            } else {
                int q2 = q - 1024;
                int t = q2 / (BNT * 4);          // 0=Bh 1=Bl
                int r = (q2 >> 2) % BNT;
                int c = q2 & 3;
                src = (t ? A.Bl : A.Bh) + (size_t)(bn + r) * DD + kt * BKK + c * 8;
                dst = sb + st * STAGEB + 2 * TILEB_A + t * TILEB_B + r * (LDT * 2) + c * 16;
            }
            cp_async16(dst, src);
        }
        cp_commit();
    };

    const int a_row = lane & 15;
    const int a_col = (lane >> 4) * 8;
    const int b_row = (lane & 7) + ((lane >> 4) << 3);
    const int b_col = ((lane >> 3) & 1) * 8;

    auto compute = [&](int kt) {
        const uint32_t base = sb + (kt % NSTG) * STAGEB;
        #pragma unroll
        for (int ks = 0; ks < 2; ks++) {
            const int k0 = ks * 16;
            uint32_t ah[4][4], al[4][4];
            #pragma unroll
            for (int mt = 0; mt < 4; mt++) {
                uint32_t off = (uint32_t)(wm + mt * 16 + a_row) * (LDT * 2)
                             + (k0 + a_col) * 2;
                ldm4(ah[mt], base + off);
                ldm4(al[mt], base + TILEB_A + off);
            }
            uint32_t bh[NJ / 2][4], bl[NJ / 2][4];
            #pragma unroll
            for (int nh = 0; nh < NJ / 2; nh++) {
                uint32_t off = (uint32_t)(wn + nh * 16 + b_row) * (LDT * 2)
                             + (k0 + b_col) * 2;
                ldm4(bh[nh], base + 2 * TILEB_A + off);
                ldm4(bl[nh], base + 2 * TILEB_A + TILEB_B + off);
            }
            #pragma unroll
            for (int mt = 0; mt < 4; mt++)
                #pragma unroll
                for (int j = 0; j < NJ; j++) {
                    const uint32_t* bhp = &bh[j >> 1][(j & 1) * 2];
                    const uint32_t* blp = &bl[j >> 1][(j & 1) * 2];
                    mma16816(acc[mt][j], ah[mt], bhp);
                    mma16816(acc[mt][j], ah[mt], blp);
                    mma16816(acc[mt][j], al[mt], bhp);
                }
        }
    };

    issue(0); issue(1); issue(2);
    for (int kt = 0; kt < NCHK; kt++) {
        if (kt + 2 < NCHK)      cp_wait<2>();
        else if (kt + 1 < NCHK) cp_wait<1>();
        else                    cp_wait<0>();
        __syncthreads();        // stage kt visible to all; all warps done with kt-1
        if (kt + 3 < NCHK) issue(kt + 3);   // overwrites stage (kt-1)%4 — safe
        compute(kt);
    }

    #pragma unroll
    for (int mt = 0; mt < 4; mt++) {
        #pragma unroll
        for (int j = 0; j < NJ; j++) {
            int row = bm + wm + mt * 16 + (lane >> 2);
            int col = bn + wn + j * 8 + (lane & 3) * 2;
            *reinterpret_cast<float2*>(A.C + (size_t)row * DD + col)
                = make_float2(acc[mt][j][0], acc[mt][j][1]);
            *reinterpret_cast<float2*>(A.C + (size_t)(row + 8) * DD + col)
                = make_float2(acc[mt][j][2], acc[mt][j][3]);
        }
    }
}

// ---------------------------------------------------------------------------
// fp32 -> (bf16 hi, bf16 lo) splits
// ---------------------------------------------------------------------------
__device__ __forceinline__ void split4(float4 v, ushort4& h, ushort4& l) {
    __nv_bfloat16 b;
    b = __float2bfloat16(v.x); h.x = __bfloat16_as_ushort(b);
    l.x = __bfloat16_as_ushort(__float2bfloat16(v.x - __bfloat162float(b)));
    b = __float2bfloat16(v.y); h.y = __bfloat16_as_ushort(b);
    l.y = __bfloat16_as_ushort(__float2bfloat16(v.y - __bfloat162float(b)));
    b = __float2bfloat16(v.z); h.z = __bfloat16_as_ushort(b);
    l.z = __bfloat16_as_ushort(__float2bfloat16(v.z - __bfloat162float(b)));
    b = __float2bfloat16(v.w); h.w = __bfloat16_as_ushort(b);
    l.w = __bfloat16_as_ushort(__float2bfloat16(v.w - __bfloat162float(b)));
}

struct SplitN {
    const float4* x[4];
    ushort4* hi[4];
    ushort4* lo[4];
};
__global__ void split_multi(SplitN a, int n4)
{
    int w = blockIdx.y;
    int i = blockIdx.x * blockDim.x + threadIdx.x;
    if (i >= n4) return;
    ushort4 h, l;
    split4(a.x[w][i], h, l);
    a.hi[w][i] = h; a.lo[w][i] = l;
}

// ---------------------------------------------------------------------------
// Vsum
// ---------------------------------------------------------------------------
__global__ void zero_vsum() {
    int i = blockIdx.x * blockDim.x + threadIdx.x;
    if (i < BB * NH * DV) g_vsum[i] = 0.0f;
}

__global__ void vsum_kernel() {
    int bh = blockIdx.x;
    int chunk = blockIdx.y;
    int b = bh / NH, h = bh % NH;
    int dv = threadIdx.x & 63;
    int sub = threadIdx.x >> 6;
    const float* vb = g_v + (size_t)b * SS * DD + h * DV;
    int s0 = chunk * (SS / 8) + sub * (SS / 32);
    float acc = 0.0f;
    for (int s = s0; s < s0 + SS / 32; s++)
        acc += vb[(size_t)s * DD + dv];
    __shared__ float red[256];
    red[threadIdx.x] = acc;
    __syncthreads();
    if (threadIdx.x < DV)
        atomicAdd(&g_vsum[bh * DV + dv],
                  red[dv] + red[64 + dv] + red[128 + dv] + red[192 + dv]);
}

// ---------------------------------------------------------------------------
// Middle rows; writes bf16 hi/lo directly (fused split for the O GEMM).
// ---------------------------------------------------------------------------
__device__ __forceinline__ void store_hl(size_t off, float v) {
    __nv_bfloat16 h = __float2bfloat16(v);
    g_ah[off] = h;
    g_al[off] = __float2bfloat16(v - __bfloat162float(h));
}

__global__ void mid_kernel(const int* __restrict__ idx)
{
    const int warps_per_block = 8;
    int item = blockIdx.x * warps_per_block + (threadIdx.x >> 5);
    const int n_items = BB * NH * SMID;
    if (item >= n_items) return;
    int lane = threadIdx.x & 31;

    int i = item % SMID;
    int h = (item / SMID) % NH;
    int b = item / (SMID * NH);
    int s = i + GG;

    const float* qrow = g_q + ((size_t)b * SS + s) * DD + h * DK;
    float q0 = qrow[lane];
    float q1 = qrow[lane + 32];

    int cols[NIDX];
    #pragma unroll
    for (int j = 0; j < NIDX; j++) cols[j] = idx[i * NIDX + j];

    // issue all K loads up front (MLP)
    float k0v[NIDX], k1v[NIDX];
    #pragma unroll
    for (int j = 0; j < NIDX; j++) {
        const float* krow = g_k + ((size_t)b * SS + cols[j]) * DD + h * DK;
        k0v[j] = krow[lane];
        k1v[j] = krow[lane + 32];
    }

    float sc[NIDX];
    #pragma unroll
    for (int j = 0; j < NIDX; j++) {
        float p = q0 * k0v[j] + q1 * k1v[j];
        #pragma unroll
        for (int o = 16; o > 0; o >>= 1) p += __shfl_xor_sync(0xFFFFFFFFu, p, o);
        sc[j] = p;
    }

    float wgt[NIDX];
    float denom = (float)SS;
    #pragma unroll
    for (int j = 0; j < NIDX; j++) {
        bool dup = false;
        #pragma unroll
        for (int jj = 0; jj < NIDX; jj++)
            if (jj < j) dup = dup || (cols[jj] == cols[j]);
        float w = dup ? 0.0f : (expf(sc[j] * 0.125f) - 1.0f);
        wgt[j] = w;
        denom += w;
    }

    const float* vs = g_vsum + (b * NH + h) * DV;
    float o0 = vs[lane];
    float o1 = vs[lane + 32];
    #pragma unroll
    for (int j = 0; j < NIDX; j++) {
        const float* vrow = g_v + ((size_t)b * SS + cols[j]) * DD + h * DV;
        o0 = fmaf(wgt[j], vrow[lane], o0);
        o1 = fmaf(wgt[j], vrow[lane + 32], o1);
    }
    float inv = 1.0f / denom;
    size_t base = ((size_t)b * SS + s) * DD + h * DV;
    store_hl(base + lane, o0 * inv);
    store_hl(base + lane + 32, o1 * inv);
}

// ---------------------------------------------------------------------------
// Global rows (s=0, s=2047): full softmax over all 2048 keys.
// ---------------------------------------------------------------------------
__global__ void global_kernel()
{
    int item = blockIdx.x;
    int r = item % 2;
    int h = (item / 2) % NH;
    int b = item / (2 * NH);
    int s = r ? (SS - 1) : 0;
    int tid = threadIdx.x;

    __shared__ float sc[SS];
    __shared__ float qs[DK];
    __shared__ float red[256];

    const float* qrow = g_q + ((size_t)b * SS + s) * DD + h * DK;
    if (tid < DK) qs[tid] = qrow[tid];
    __syncthreads();

    for (int t = tid; t < SS; t += 256) {
        const float* krow = g_k + ((size_t)b * SS + t) * DD + h * DK;
        float p = 0.0f;
        #pragma unroll
        for (int d = 0; d < DK; d++) p = fmaf(qs[d], krow[d], p);
        sc[t] = p * 0.125f;
    }
    __syncthreads();

    float m = -1e30f;
    for (int t = tid; t < SS; t += 256) m = fmaxf(m, sc[t]);
    red[tid] = m; __syncthreads();
    for (int o = 128; o > 0; o >>= 1) {
        if (tid < o) red[tid] = fmaxf(red[tid], red[tid + o]);
        __syncthreads();
    }
    m = red[0];
    __syncthreads();

    float sum = 0.0f;
    for (int t = tid; t < SS; t += 256) {
        float e = expf(sc[t] - m);
        sc[t] = e;
        sum += e;
    }
    red[tid] = sum; __syncthreads();
    for (int o = 128; o > 0; o >>= 1) {
        if (tid < o) red[tid] += red[tid + o];
        __syncthreads();
    }
    float inv = 1.0f / red[0];
    __syncthreads();

    int dv = tid % DV;
    int chunk = tid / DV;
    float acc = 0.0f;
    const float* vb = g_v + (size_t)b * SS * DD + h * DV + dv;
    for (int t = chunk * (SS / 4); t < (chunk + 1) * (SS / 4); t++)
        acc = fmaf(sc[t], vb[(size_t)t * DD], acc);
    red[tid] = acc; __syncthreads();
    if (tid < DV) {
        float o = (red[dv] + red[DV + dv] + red[2 * DV + dv] + red[3 * DV + dv]) * inv;
        store_hl(((size_t)b * SS + s) * DD + h * DV + dv, o);
    }
}

// ---------------------------------------------------------------------------
extern "C" void kernel_launch(void* const* d_in, const int* in_sizes, int n_in,
                              void* d_out, int out_size)
{
    const float* Q  = (const float*)d_in[0];
    const float* K  = (const float*)d_in[1];
    const float* V  = (const float*)d_in[2];
    const float* Wq = (const float*)d_in[3];
    const float* Wk = (const float*)d_in[4];
    const float* Wv = (const float*)d_in[5];
    const float* Wo = (const float*)d_in[6];
    const int*   idx = (const int*)d_in[7];
    float* out = (float*)d_out;

    float *pq, *pk, *pv;
    cudaGetSymbolAddress((void**)&pq, g_q);
    cudaGetSymbolAddress((void**)&pk, g_k);
    cudaGetSymbolAddress((void**)&pv, g_v);

    __nv_bfloat16 *qh, *ql, *kh, *kl, *vh, *vl, *ah, *al;
    __nv_bfloat16 *wqh, *wql, *wkh, *wkl, *wvh, *wvl, *woh, *wol;
    cudaGetSymbolAddress((void**)&qh, g_qh);  cudaGetSymbolAddress((void**)&ql, g_ql);
    cudaGetSymbolAddress((void**)&kh, g_kh);  cudaGetSymbolAddress((void**)&kl, g_kl);
    cudaGetSymbolAddress((void**)&vh, g_vh);  cudaGetSymbolAddress((void**)&vl, g_vl);
    cudaGetSymbolAddress((void**)&ah, g_ah);  cudaGetSymbolAddress((void**)&al, g_al);
    cudaGetSymbolAddress((void**)&wqh, g_wqh); cudaGetSymbolAddress((void**)&wql, g_wql);
    cudaGetSymbolAddress((void**)&wkh, g_wkh); cudaGetSymbolAddress((void**)&wkl, g_wkl);
    cudaGetSymbolAddress((void**)&wvh, g_wvh); cudaGetSymbolAddress((void**)&wvl, g_wvl);
    cudaGetSymbolAddress((void**)&woh, g_woh); cudaGetSymbolAddress((void**)&wol, g_wol);

    constexpr int SMEM128 = NSTG * (2 * 128 * LDT * 2 + 2 * 128 * LDT * 2); // 163840
    constexpr int SMEM64  = NSTG * (2 * 128 * LDT * 2 + 2 * 64 * LDT * 2);  // 122880
    cudaFuncSetAttribute(gemm_mma<128>, cudaFuncAttributeMaxDynamicSharedMemorySize, SMEM128);
    cudaFuncSetAttribute(gemm_mma<64>,  cudaFuncAttributeMaxDynamicSharedMemorySize, SMEM64);

    const int n4_big = MROWS * DD / 4;
    const int n4_w   = DD * DD / 4;
    const int bl_big = (n4_big + 255) / 256;
    const int bl_w   = (n4_w + 255) / 256;

    zero_vsum<<<6, 256>>>();

    SplitN si;
    si.x[0] = (const float4*)Q; si.hi[0] = (ushort4*)qh; si.lo[0] = (ushort4*)ql;
    si.x[1] = (const float4*)K; si.hi[1] = (ushort4*)kh; si.lo[1] = (ushort4*)kl;
    si.x[2] = (const float4*)V; si.hi[2] = (ushort4*)vh; si.lo[2] = (ushort4*)vl;
    si.x[3] = si.x[0]; si.hi[3] = si.hi[0]; si.lo[3] = si.lo[0];
    split_multi<<<dim3(bl_big, 3), 256>>>(si, n4_big);

    SplitN sw;
    sw.x[0] = (const float4*)Wq; sw.hi[0] = (ushort4*)wqh; sw.lo[0] = (ushort4*)wql;
    sw.x[1] = (const float4*)Wk; sw.hi[1] = (ushort4*)wkh; sw.lo[1] = (ushort4*)wkl;
    sw.x[2] = (const float4*)Wv; sw.hi[2] = (ushort4*)wvh; sw.lo[2] = (ushort4*)wvl;
    sw.x[3] = (const float4*)Wo; sw.hi[3] = (ushort4*)woh; sw.lo[3] = (ushort4*)wol;
    split_multi<<<dim3(bl_w, 4), 256>>>(sw, n4_w);

    Gemm3 g3;
    g3.g[0] = {qh, ql, wqh, wql, pq};
    g3.g[1] = {kh, kl, wkh, wkl, pk};
    g3.g[2] = {vh, vl, wvh, wvl, pv};
    gemm_mma<128><<<dim3(DD / 128, MROWS / BM, 3), 256, SMEM128>>>(g3);

    vsum_kernel<<<dim3(BB * NH, 8), 256>>>();
    const int n_items = BB * NH * SMID;
    mid_kernel<<<(n_items + 7) / 8, 256>>>(idx);
    global_kernel<<<BB * NH * 2, 256>>>();

    Gemm3 go;
    go.g[0] = {ah, al, woh, wol, out};
    go.g[1] = go.g[0];
    go.g[2] = go.g[0];
    gemm_mma<64><<<dim3(DD / 64, MROWS / BM, 1), 256, SMEM64>>>(go);
}

// round 6
// speedup vs baseline: 1.0832x; 1.0832x over previous
#include <cuda_runtime.h>
#include <cuda_bf16.h>
#include <cstdint>
#include <math.h>

// Problem constants
#define BB 2
#define SS 2048
#define DD 768
#define NH 12
#define DK 64
#define DV 64
#define GG 1
#define NIDX 6
#define SMID (SS - 2*GG)
#define MROWS (BB * SS)

// GEMM tiling
#define BM 128
#define BKK 32                    // bf16 K elems per stage
#define NCHK (DD / BKK)           // 24 k-iterations
#define LDT 40                    // padded row stride (elements): 80B
#define NSTG 2

// ---------------------------------------------------------------------------
// Scratch
// ---------------------------------------------------------------------------
__device__ float g_q[MROWS * DD];
__device__ float g_k[MROWS * DD];
__device__ float g_v[MROWS * DD];
__device__ float g_vsum[BB * NH * DV];

__device__ __nv_bfloat16 g_qh[MROWS * DD], g_ql[MROWS * DD];
__device__ __nv_bfloat16 g_kh[MROWS * DD], g_kl[MROWS * DD];
__device__ __nv_bfloat16 g_vh[MROWS * DD], g_vl[MROWS * DD];
__device__ __nv_bfloat16 g_ah[MROWS * DD], g_al[MROWS * DD];
__device__ __nv_bfloat16 g_wqh[DD * DD], g_wql[DD * DD];
__device__ __nv_bfloat16 g_wkh[DD * DD], g_wkl[DD * DD];
__device__ __nv_bfloat16 g_wvh[DD * DD], g_wvl[DD * DD];
__device__ __nv_bfloat16 g_woh[DD * DD], g_wol[DD * DD];

// ---------------------------------------------------------------------------
// PTX helpers (portable sm_80+ ISA)
// ---------------------------------------------------------------------------
__device__ __forceinline__ uint32_t smem_u32(const void* p) {
    uint32_t a;
    asm("{ .reg .u64 t; cvta.to.shared.u64 t, %1; cvt.u32.u64 %0, t; }"
        : "=r"(a) : "l"(p));
    return a;
}
__device__ __forceinline__ void cp_async16(uint32_t dst, const void* src) {
    asm volatile("cp.async.cg.shared.global [%0], [%1], 16;"
                 :: "r"(dst), "l"(src) : "memory");
}
__device__ __forceinline__ void cp_commit() {
    asm volatile("cp.async.commit_group;" ::: "memory");
}
template <int N>
__device__ __forceinline__ void cp_wait() {
    asm volatile("cp.async.wait_group %0;" :: "n"(N) : "memory");
}
__device__ __forceinline__ void ldm4(uint32_t* r, uint32_t addr) {
    asm volatile("ldmatrix.sync.aligned.m8n8.x4.shared.b16 {%0,%1,%2,%3}, [%4];"
                 : "=r"(r[0]), "=r"(r[1]), "=r"(r[2]), "=r"(r[3]) : "r"(addr));
}
__device__ __forceinline__ void mma16816(float* c, const uint32_t* a, const uint32_t* b) {
    asm volatile(
        "mma.sync.aligned.m16n8k16.row.col.f32.bf16.bf16.f32 "
        "{%0,%1,%2,%3}, {%4,%5,%6,%7}, {%8,%9}, {%0,%1,%2,%3};"
        : "+f"(c[0]), "+f"(c[1]), "+f"(c[2]), "+f"(c[3])
        : "r"(a[0]), "r"(a[1]), "r"(a[2]), "r"(a[3]), "r"(b[0]), "r"(b[1]));
}

struct GemmArgs {
    const __nv_bfloat16 *Ah, *Al, *Bh, *Bl;
    float* C;
};
struct Gemm3 { GemmArgs g[3]; };

// ---------------------------------------------------------------------------
// C[M,768] = Ah*Bh^T + Ah*Bl^T + Al*Bh^T  (bf16 split-fp32), B is [768,768]
// Template on BNT (CTA N-tile). 8 warps, 2m x (BNT/WNT)n layout.
// NSTG=2 cp.async stages, 2 CTAs/SM (the key change this round).
// ---------------------------------------------------------------------------
template <int BNT>
__global__ __launch_bounds__(256, 2) void gemm_mma(Gemm3 ga)
{
    constexpr int WNT = BNT / 4;                 // warp n-tile (32 or 16)
    constexpr int NJ = WNT / 8;                  // n8 tiles per warp (4 or 2)
    constexpr int TILEB_A = 128 * LDT * 2;       // 10240
    constexpr int TILEB_B = BNT * LDT * 2;
    constexpr int STAGEB = 2 * TILEB_A + 2 * TILEB_B;
    constexpr int NCHUNK = (2 * 128 + 2 * BNT) * 4;   // 16B chunks per stage
    constexpr int PER_THR = NCHUNK / 256;

    extern __shared__ char smem[];
    const GemmArgs& A = ga.g[blockIdx.z];
    const uint32_t sb = smem_u32(smem);
    const int tid = threadIdx.x;
    const int wid = tid >> 5;
    const int lane = tid & 31;
    const int bm = blockIdx.y * BM;
    const int bn = blockIdx.x * BNT;
    const int wm = (wid >> 2) * 64;
    const int wn = (wid & 3) * WNT;

    float acc[4][NJ][4];
    #pragma unroll
    for (int i = 0; i < 4; i++)
        #pragma unroll
        for (int j = 0; j < NJ; j++)
            #pragma unroll
            for (int e = 0; e < 4; e++) acc[i][j][e] = 0.0f;

    // chunk layout: [Ah(512) | Al(512) | Bh(BNT*4) | Bl(BNT*4)]
    auto issue = [&](int kt) {
        const int st = kt % NSTG;
        #pragma unroll
        for (int q8 = 0; q8 < PER_THR; q8++) {
            int q = tid + q8 * 256;
            const __nv_bfloat16* src;
            uint32_t dst;
            if (q < 1024) {
                int t = q >> 9;                  // 0=Ah 1=Al
                int r = (q >> 2) & 127;
                int c = q & 3;
                src = (t ? A.Al : A.Ah) + (size_t)(bm + r) * DD + kt * BKK + c * 8;
                dst = sb + st * STAGEB + t * TILEB_A + r * (LDT * 2) + c * 16;
            } else {
                int q2 = q - 1024;
                int t = q2 / (BNT * 4);          // 0=Bh 1=Bl
                int r = (q2 >> 2) % BNT;
                int c = q2 & 3;
                src = (t ? A.Bl : A.Bh) + (size_t)(bn + r) * DD + kt * BKK + c * 8;
                dst = sb + st * STAGEB + 2 * TILEB_A + t * TILEB_B + r * (LDT * 2) + c * 16;
            }
            cp_async16(dst, src);
        }
        cp_commit();
    };

    const int a_row = lane & 15;
    const int a_col = (lane >> 4) * 8;
    const int b_row = (lane & 7) + ((lane >> 4) << 3);
    const int b_col = ((lane >> 3) & 1) * 8;

    auto compute = [&](int kt) {
        const uint32_t base = sb + (kt % NSTG) * STAGEB;
        #pragma unroll
        for (int ks = 0; ks < 2; ks++) {
            const int k0 = ks * 16;
            uint32_t ah[4][4], al[4][4];
            #pragma unroll
            for (int mt = 0; mt < 4; mt++) {
                uint32_t off = (uint32_t)(wm + mt * 16 + a_row) * (LDT * 2)
                             + (k0 + a_col) * 2;
                ldm4(ah[mt], base + off);
                ldm4(al[mt], base + TILEB_A + off);
            }
            uint32_t bh[NJ / 2][4], bl[NJ / 2][4];
            #pragma unroll
            for (int nh = 0; nh < NJ / 2; nh++) {
                uint32_t off = (uint32_t)(wn + nh * 16 + b_row) * (LDT * 2)
                             + (k0 + b_col) * 2;
                ldm4(bh[nh], base + 2 * TILEB_A + off);
                ldm4(bl[nh], base + 2 * TILEB_A + TILEB_B + off);
            }
            #pragma unroll
            for (int mt = 0; mt < 4; mt++)
                #pragma unroll
                for (int j = 0; j < NJ; j++) {
                    const uint32_t* bhp = &bh[j >> 1][(j & 1) * 2];
                    const uint32_t* blp = &bl[j >> 1][(j & 1) * 2];
                    mma16816(acc[mt][j], ah[mt], bhp);
                    mma16816(acc[mt][j], ah[mt], blp);
                    mma16816(acc[mt][j], al[mt], bhp);
                }
        }
    };

    issue(0);
    for (int kt = 0; kt < NCHK; kt++) {
        cp_wait<0>();
        __syncthreads();        // stage kt loaded; all warps done with compute(kt-1)
        if (kt + 1 < NCHK) issue(kt + 1);   // overwrites stage (kt-1)%2 — safe
        compute(kt);
    }

    #pragma unroll
    for (int mt = 0; mt < 4; mt++) {
        #pragma unroll
        for (int j = 0; j < NJ; j++) {
            int row = bm + wm + mt * 16 + (lane >> 2);
            int col = bn + wn + j * 8 + (lane & 3) * 2;
            *reinterpret_cast<float2*>(A.C + (size_t)row * DD + col)
                = make_float2(acc[mt][j][0], acc[mt][j][1]);
            *reinterpret_cast<float2*>(A.C + (size_t)(row + 8) * DD + col)
                = make_float2(acc[mt][j][2], acc[mt][j][3]);
        }
    }
}

// ---------------------------------------------------------------------------
// fp32 -> (bf16 hi, bf16 lo) splits
// ---------------------------------------------------------------------------
__device__ __forceinline__ void split4(float4 v, ushort4& h, ushort4& l) {
    __nv_bfloat16 b;
    b = __float2bfloat16(v.x); h.x = __bfloat16_as_ushort(b);
    l.x = __bfloat16_as_ushort(__float2bfloat16(v.x - __bfloat162float(b)));
    b = __float2bfloat16(v.y); h.y = __bfloat16_as_ushort(b);
    l.y = __bfloat16_as_ushort(__float2bfloat16(v.y - __bfloat162float(b)));
    b = __float2bfloat16(v.z); h.z = __bfloat16_as_ushort(b);
    l.z = __bfloat16_as_ushort(__float2bfloat16(v.z - __bfloat162float(b)));
    b = __float2bfloat16(v.w); h.w = __bfloat16_as_ushort(b);
    l.w = __bfloat16_as_ushort(__float2bfloat16(v.w - __bfloat162float(b)));
}

struct SplitN {
    const float4* x[4];
    ushort4* hi[4];
    ushort4* lo[4];
};
__global__ void split_multi(SplitN a, int n4)
{
    int w = blockIdx.y;
    int i = blockIdx.x * blockDim.x + threadIdx.x;
    if (i >= n4) return;
    ushort4 h, l;
    split4(a.x[w][i], h, l);
    a.hi[w][i] = h; a.lo[w][i] = l;
}

// ---------------------------------------------------------------------------
// Vsum
// ---------------------------------------------------------------------------
__global__ void zero_vsum() {
    int i = blockIdx.x * blockDim.x + threadIdx.x;
    if (i < BB * NH * DV) g_vsum[i] = 0.0f;
}

__global__ void vsum_kernel() {
    int bh = blockIdx.x;
    int chunk = blockIdx.y;
    int b = bh / NH, h = bh % NH;
    int dv = threadIdx.x & 63;
    int sub = threadIdx.x >> 6;
    const float* vb = g_v + (size_t)b * SS * DD + h * DV;
    int s0 = chunk * (SS / 8) + sub * (SS / 32);
    float acc = 0.0f;
    for (int s = s0; s < s0 + SS / 32; s++)
        acc += vb[(size_t)s * DD + dv];
    __shared__ float red[256];
    red[threadIdx.x] = acc;
    __syncthreads();
    if (threadIdx.x < DV)
        atomicAdd(&g_vsum[bh * DV + dv],
                  red[dv] + red[64 + dv] + red[128 + dv] + red[192 + dv]);
}

// ---------------------------------------------------------------------------
// Middle rows; writes bf16 hi/lo directly (fused split for the O GEMM).
// ---------------------------------------------------------------------------
__device__ __forceinline__ void store_hl(size_t off, float v) {
    __nv_bfloat16 h = __float2bfloat16(v);
    g_ah[off] = h;
    g_al[off] = __float2bfloat16(v - __bfloat162float(h));
}

__global__ void mid_kernel(const int* __restrict__ idx)
{
    const int warps_per_block = 8;
    int item = blockIdx.x * warps_per_block + (threadIdx.x >> 5);
    const int n_items = BB * NH * SMID;
    if (item >= n_items) return;
    int lane = threadIdx.x & 31;

    int i = item % SMID;
    int h = (item / SMID) % NH;
    int b = item / (SMID * NH);
    int s = i + GG;

    const float* qrow = g_q + ((size_t)b * SS + s) * DD + h * DK;
    float q0 = qrow[lane];
    float q1 = qrow[lane + 32];

    int cols[NIDX];
    #pragma unroll
    for (int j = 0; j < NIDX; j++) cols[j] = idx[i * NIDX + j];

    float k0v[NIDX], k1v[NIDX];
    #pragma unroll
    for (int j = 0; j < NIDX; j++) {
        const float* krow = g_k + ((size_t)b * SS + cols[j]) * DD + h * DK;
        k0v[j] = krow[lane];
        k1v[j] = krow[lane + 32];
    }

    float sc[NIDX];
    #pragma unroll
    for (int j = 0; j < NIDX; j++) {
        float p = q0 * k0v[j] + q1 * k1v[j];
        #pragma unroll
        for (int o = 16; o > 0; o >>= 1) p += __shfl_xor_sync(0xFFFFFFFFu, p, o);
        sc[j] = p;
    }

    float wgt[NIDX];
    float denom = (float)SS;
    #pragma unroll
    for (int j = 0; j < NIDX; j++) {
        bool dup = false;
        #pragma unroll
        for (int jj = 0; jj < NIDX; jj++)
            if (jj < j) dup = dup || (cols[jj] == cols[j]);
        float w = dup ? 0.0f : (expf(sc[j] * 0.125f) - 1.0f);
        wgt[j] = w;
        denom += w;
    }

    const float* vs = g_vsum + (b * NH + h) * DV;
    float o0 = vs[lane];
    float o1 = vs[lane + 32];
    #pragma unroll
    for (int j = 0; j < NIDX; j++) {
        const float* vrow = g_v + ((size_t)b * SS + cols[j]) * DD + h * DV;
        o0 = fmaf(wgt[j], vrow[lane], o0);
        o1 = fmaf(wgt[j], vrow[lane + 32], o1);
    }
    float inv = 1.0f / denom;
    size_t base = ((size_t)b * SS + s) * DD + h * DV;
    store_hl(base + lane, o0 * inv);
    store_hl(base + lane + 32, o1 * inv);
}

// ---------------------------------------------------------------------------
// Global rows (s=0, s=2047): full softmax over all 2048 keys.
// ---------------------------------------------------------------------------
__global__ void global_kernel()
{
    int item = blockIdx.x;
    int r = item % 2;
    int h = (item / 2) % NH;
    int b = item / (2 * NH);
    int s = r ? (SS - 1) : 0;
    int tid = threadIdx.x;

    __shared__ float sc[SS];
    __shared__ float qs[DK];
    __shared__ float red[256];

    const float* qrow = g_q + ((size_t)b * SS + s) * DD + h * DK;
    if (tid < DK) qs[tid] = qrow[tid];
    __syncthreads();

    for (int t = tid; t < SS; t += 256) {
        const float* krow = g_k + ((size_t)b * SS + t) * DD + h * DK;
        float p = 0.0f;
        #pragma unroll
        for (int d = 0; d < DK; d++) p = fmaf(qs[d], krow[d], p);
        sc[t] = p * 0.125f;
    }
    __syncthreads();

    float m = -1e30f;
    for (int t = tid; t < SS; t += 256) m = fmaxf(m, sc[t]);
    red[tid] = m; __syncthreads();
    for (int o = 128; o > 0; o >>= 1) {
        if (tid < o) red[tid] = fmaxf(red[tid], red[tid + o]);
        __syncthreads();
    }
    m = red[0];
    __syncthreads();

    float sum = 0.0f;
    for (int t = tid; t < SS; t += 256) {
        float e = expf(sc[t] - m);
        sc[t] = e;
        sum += e;
    }
    red[tid] = sum; __syncthreads();
    for (int o = 128; o > 0; o >>= 1) {
        if (tid < o) red[tid] += red[tid + o];
        __syncthreads();
    }
    float inv = 1.0f / red[0];
    __syncthreads();

    int dv = tid % DV;
    int chunk = tid / DV;
    float acc = 0.0f;
    const float* vb = g_v + (size_t)b * SS * DD + h * DV + dv;
    for (int t = chunk * (SS / 4); t < (chunk + 1) * (SS / 4); t++)
        acc = fmaf(sc[t], vb[(size_t)t * DD], acc);
    red[tid] = acc; __syncthreads();
    if (tid < DV) {
        float o = (red[dv] + red[DV + dv] + red[2 * DV + dv] + red[3 * DV + dv]) * inv;
        store_hl(((size_t)b * SS + s) * DD + h * DV + dv, o);
    }
}

// ---------------------------------------------------------------------------
extern "C" void kernel_launch(void* const* d_in, const int* in_sizes, int n_in,
                              void* d_out, int out_size)
{
    const float* Q  = (const float*)d_in[0];
    const float* K  = (const float*)d_in[1];
    const float* V  = (const float*)d_in[2];
    const float* Wq = (const float*)d_in[3];
    const float* Wk = (const float*)d_in[4];
    const float* Wv = (const float*)d_in[5];
    const float* Wo = (const float*)d_in[6];
    const int*   idx = (const int*)d_in[7];
    float* out = (float*)d_out;

    float *pq, *pk, *pv;
    cudaGetSymbolAddress((void**)&pq, g_q);
    cudaGetSymbolAddress((void**)&pk, g_k);
    cudaGetSymbolAddress((void**)&pv, g_v);

    __nv_bfloat16 *qh, *ql, *kh, *kl, *vh, *vl, *ah, *al;
    __nv_bfloat16 *wqh, *wql, *wkh, *wkl, *wvh, *wvl, *woh, *wol;
    cudaGetSymbolAddress((void**)&qh, g_qh);  cudaGetSymbolAddress((void**)&ql, g_ql);
    cudaGetSymbolAddress((void**)&kh, g_kh);  cudaGetSymbolAddress((void**)&kl, g_kl);
    cudaGetSymbolAddress((void**)&vh, g_vh);  cudaGetSymbolAddress((void**)&vl, g_vl);
    cudaGetSymbolAddress((void**)&ah, g_ah);  cudaGetSymbolAddress((void**)&al, g_al);
    cudaGetSymbolAddress((void**)&wqh, g_wqh); cudaGetSymbolAddress((void**)&wql, g_wql);
    cudaGetSymbolAddress((void**)&wkh, g_wkh); cudaGetSymbolAddress((void**)&wkl, g_wkl);
    cudaGetSymbolAddress((void**)&wvh, g_wvh); cudaGetSymbolAddress((void**)&wvl, g_wvl);
    cudaGetSymbolAddress((void**)&woh, g_woh); cudaGetSymbolAddress((void**)&wol, g_wol);

    constexpr int SMEM128 = NSTG * (2 * 128 * LDT * 2 + 2 * 128 * LDT * 2); // 81920
    constexpr int SMEM64  = NSTG * (2 * 128 * LDT * 2 + 2 * 64 * LDT * 2);  // 61440
    cudaFuncSetAttribute(gemm_mma<128>, cudaFuncAttributeMaxDynamicSharedMemorySize, SMEM128);
    cudaFuncSetAttribute(gemm_mma<64>,  cudaFuncAttributeMaxDynamicSharedMemorySize, SMEM64);

    const int n4_big = MROWS * DD / 4;
    const int n4_w   = DD * DD / 4;
    const int bl_big = (n4_big + 255) / 256;
    const int bl_w   = (n4_w + 255) / 256;

    zero_vsum<<<6, 256>>>();

    SplitN si;
    si.x[0] = (const float4*)Q; si.hi[0] = (ushort4*)qh; si.lo[0] = (ushort4*)ql;
    si.x[1] = (const float4*)K; si.hi[1] = (ushort4*)kh; si.lo[1] = (ushort4*)kl;
    si.x[2] = (const float4*)V; si.hi[2] = (ushort4*)vh; si.lo[2] = (ushort4*)vl;
    si.x[3] = si.x[0]; si.hi[3] = si.hi[0]; si.lo[3] = si.lo[0];
    split_multi<<<dim3(bl_big, 3), 256>>>(si, n4_big);

    SplitN sw;
    sw.x[0] = (const float4*)Wq; sw.hi[0] = (ushort4*)wqh; sw.lo[0] = (ushort4*)wql;
    sw.x[1] = (const float4*)Wk; sw.hi[1] = (ushort4*)wkh; sw.lo[1] = (ushort4*)wkl;
    sw.x[2] = (const float4*)Wv; sw.hi[2] = (ushort4*)wvh; sw.lo[2] = (ushort4*)wvl;
    sw.x[3] = (const float4*)Wo; sw.hi[3] = (ushort4*)woh; sw.lo[3] = (ushort4*)wol;
    split_multi<<<dim3(bl_w, 4), 256>>>(sw, n4_w);

    Gemm3 g3;
    g3.g[0] = {qh, ql, wqh, wql, pq};
    g3.g[1] = {kh, kl, wkh, wkl, pk};
    g3.g[2] = {vh, vl, wvh, wvl, pv};
    gemm_mma<128><<<dim3(DD / 128, MROWS / BM, 3), 256, SMEM128>>>(g3);

    vsum_kernel<<<dim3(BB * NH, 8), 256>>>();
    const int n_items = BB * NH * SMID;
    mid_kernel<<<(n_items + 7) / 8, 256>>>(idx);
    global_kernel<<<BB * NH * 2, 256>>>();

    Gemm3 go;
    go.g[0] = {ah, al, woh, wol, out};
    go.g[1] = go.g[0];
    go.g[2] = go.g[0];
    gemm_mma<64><<<dim3(DD / 64, MROWS / BM, 1), 256, SMEM64>>>(go);
}

// round 7
// speedup vs baseline: 1.1453x; 1.0574x over previous
#include <cuda_runtime.h>
#include <cuda_fp16.h>
#include <cstdint>
#include <math.h>

// Problem constants
#define BB 2
#define SS 2048
#define DD 768
#define NH 12
#define DK 64
#define DV 64
#define GG 1
#define NIDX 6
#define SMID (SS - 2*GG)
#define MROWS (BB * SS)

// GEMM tiling
#define BM 128
#define BKK 32                    // f16 K elems per stage
#define NCHK (DD / BKK)           // 24 k-iterations
#define LDT 40                    // padded row stride (elements): 80B
#define NSTG 2

// ---------------------------------------------------------------------------
// Scratch
// ---------------------------------------------------------------------------
__device__ float g_q[MROWS * DD];
__device__ float g_k[MROWS * DD];
__device__ float g_v[MROWS * DD];
__device__ float g_vsum[BB * DD];

__device__ __half g_qh[MROWS * DD];
__device__ __half g_kh[MROWS * DD];
__device__ __half g_vh[MROWS * DD], g_vl[MROWS * DD];
__device__ __half g_ah[MROWS * DD], g_al[MROWS * DD];
__device__ __half g_wqh[DD * DD], g_wql[DD * DD];
__device__ __half g_wkh[DD * DD], g_wkl[DD * DD];
__device__ __half g_wvh[DD * DD], g_wvl[DD * DD];
__device__ __half g_woh[DD * DD], g_wol[DD * DD];

// ---------------------------------------------------------------------------
// PTX helpers (portable sm_80+ ISA)
// ---------------------------------------------------------------------------
__device__ __forceinline__ uint32_t smem_u32(const void* p) {
    uint32_t a;
    asm("{ .reg .u64 t; cvta.to.shared.u64 t, %1; cvt.u32.u64 %0, t; }"
        : "=r"(a) : "l"(p));
    return a;
}
__device__ __forceinline__ void cp_async16(uint32_t dst, const void* src) {
    asm volatile("cp.async.cg.shared.global [%0], [%1], 16;"
                 :: "r"(dst), "l"(src) : "memory");
}
__device__ __forceinline__ void cp_commit() {
    asm volatile("cp.async.commit_group;" ::: "memory");
}
template <int N>
__device__ __forceinline__ void cp_wait() {
    asm volatile("cp.async.wait_group %0;" :: "n"(N) : "memory");
}
__device__ __forceinline__ void ldm4(uint32_t* r, uint32_t addr) {
    asm volatile("ldmatrix.sync.aligned.m8n8.x4.shared.b16 {%0,%1,%2,%3}, [%4];"
                 : "=r"(r[0]), "=r"(r[1]), "=r"(r[2]), "=r"(r[3]) : "r"(addr));
}
__device__ __forceinline__ void mma16816(float* c, const uint32_t* a, const uint32_t* b) {
    asm volatile(
        "mma.sync.aligned.m16n8k16.row.col.f32.f16.f16.f32 "
        "{%0,%1,%2,%3}, {%4,%5,%6,%7}, {%8,%9}, {%0,%1,%2,%3};"
        : "+f"(c[0]), "+f"(c[1]), "+f"(c[2]), "+f"(c[3])
        : "r"(a[0]), "r"(a[1]), "r"(a[2]), "r"(a[3]), "r"(b[0]), "r"(b[1]));
}

struct GemmArgs {
    const __half *Ah, *Al, *Bh, *Bl;
    float* C;
    float* vsum;     // non-null: accumulate per-batch column sums (V GEMM)
    int np3;         // 1: three products (…+ Al*Bh); 0: two products
};
struct Gemm3 { GemmArgs g[3]; };

// ---------------------------------------------------------------------------
// C[M,768] = Ah*Bh^T + Ah*Bl^T (+ Al*Bh^T)  (f16 split-fp32), B is [768,768]
// Template on BNT (CTA N-tile). 8 warps, 2m x 4n layout, NSTG=2, 2 CTAs/SM.
// ---------------------------------------------------------------------------
template <int BNT>
__global__ __launch_bounds__(256, 2) void gemm_mma(Gemm3 ga)
{
    constexpr int WNT = BNT / 4;                 // warp n-tile (32 or 16)
    constexpr int NJ = WNT / 8;                  // n8 tiles per warp (4 or 2)
    constexpr int TILEB_A = 128 * LDT * 2;       // 10240
    constexpr int TILEB_B = BNT * LDT * 2;
    constexpr int STAGEB = 2 * TILEB_A + 2 * TILEB_B;
    constexpr int NCHUNK = (2 * 128 + 2 * BNT) * 4;   // 16B chunks per stage
    constexpr int PER_THR = NCHUNK / 256;

    extern __shared__ char smem[];
    const GemmArgs& A = ga.g[blockIdx.z];
    const bool np3 = (A.np3 != 0);
    const uint32_t sb = smem_u32(smem);
    const int tid = threadIdx.x;
    const int wid = tid >> 5;
    const int lane = tid & 31;
    const int bm = blockIdx.y * BM;
    const int bn = blockIdx.x * BNT;
    const int wm = (wid >> 2) * 64;
    const int wn = (wid & 3) * WNT;

    float acc[4][NJ][4];
    #pragma unroll
    for (int i = 0; i < 4; i++)
        #pragma unroll
        for (int j = 0; j < NJ; j++)
            #pragma unroll
            for (int e = 0; e < 4; e++) acc[i][j][e] = 0.0f;

    // chunk layout: [Ah(512) | Al(512) | Bh(BNT*4) | Bl(BNT*4)]
    auto issue = [&](int kt) {
        const int st = kt % NSTG;
        #pragma unroll
        for (int q8 = 0; q8 < PER_THR; q8++) {
            int q = tid + q8 * 256;
            if (q < 1024) {
                int t = q >> 9;                  // 0=Ah 1=Al
                if (t == 1 && !np3) continue;    // 2-product: no A-lo tile
                int r = (q >> 2) & 127;
                int c = q & 3;
                const __half* src = (t ? A.Al : A.Ah)
                                    + (size_t)(bm + r) * DD + kt * BKK + c * 8;
                uint32_t dst = sb + st * STAGEB + t * TILEB_A + r * (LDT * 2) + c * 16;
                cp_async16(dst, src);
            } else {
                int q2 = q - 1024;
                int t = q2 / (BNT * 4);          // 0=Bh 1=Bl
                int r = (q2 >> 2) % BNT;
                int c = q2 & 3;
                const __half* src = (t ? A.Bl : A.Bh)
                                    + (size_t)(bn + r) * DD + kt * BKK + c * 8;
                uint32_t dst = sb + st * STAGEB + 2 * TILEB_A + t * TILEB_B
                             + r * (LDT * 2) + c * 16;
                cp_async16(dst, src);
            }
        }
        cp_commit();
    };

    const int a_row = lane & 15;
    const int a_col = (lane >> 4) * 8;
    const int b_row = (lane & 7) + ((lane >> 4) << 3);
    const int b_col = ((lane >> 3) & 1) * 8;

    auto compute = [&](int kt) {
        const uint32_t base = sb + (kt % NSTG) * STAGEB;
        #pragma unroll
        for (int ks = 0; ks < 2; ks++) {
            const int k0 = ks * 16;
            uint32_t bh[NJ / 2][4], bl[NJ / 2][4];
            #pragma unroll
            for (int nh = 0; nh < NJ / 2; nh++) {
                uint32_t off = (uint32_t)(wn + nh * 16 + b_row) * (LDT * 2)
                             + (k0 + b_col) * 2;
                ldm4(bh[nh], base + 2 * TILEB_A + off);
                ldm4(bl[nh], base + 2 * TILEB_A + TILEB_B + off);
            }
            uint32_t af[4][4];
            #pragma unroll
            for (int mt = 0; mt < 4; mt++) {
                uint32_t off = (uint32_t)(wm + mt * 16 + a_row) * (LDT * 2)
                             + (k0 + a_col) * 2;
                ldm4(af[mt], base + off);
            }
            #pragma unroll
            for (int mt = 0; mt < 4; mt++)
                #pragma unroll
                for (int j = 0; j < NJ; j++) {
                    const uint32_t* bhp = &bh[j >> 1][(j & 1) * 2];
                    const uint32_t* blp = &bl[j >> 1][(j & 1) * 2];
                    mma16816(acc[mt][j], af[mt], bhp);
                    mma16816(acc[mt][j], af[mt], blp);
                }
            if (np3) {   // third product: Al * Bh (reload af with A-lo)
                #pragma unroll
                for (int mt = 0; mt < 4; mt++) {
                    uint32_t off = (uint32_t)(wm + mt * 16 + a_row) * (LDT * 2)
                                 + (k0 + a_col) * 2;
                    ldm4(af[mt], base + TILEB_A + off);
                }
                #pragma unroll
                for (int mt = 0; mt < 4; mt++)
                    #pragma unroll
                    for (int j = 0; j < NJ; j++)
                        mma16816(acc[mt][j], af[mt], &bh[j >> 1][(j & 1) * 2]);
            }
        }
    };

    issue(0);
    for (int kt = 0; kt < NCHK; kt++) {
        cp_wait<0>();
        __syncthreads();
        if (kt + 1 < NCHK) issue(kt + 1);
        compute(kt);
    }

    #pragma unroll
    for (int mt = 0; mt < 4; mt++) {
        #pragma unroll
        for (int j = 0; j < NJ; j++) {
            int row = bm + wm + mt * 16 + (lane >> 2);
            int col = bn + wn + j * 8 + (lane & 3) * 2;
            *reinterpret_cast<float2*>(A.C + (size_t)row * DD + col)
                = make_float2(acc[mt][j][0], acc[mt][j][1]);
            *reinterpret_cast<float2*>(A.C + (size_t)(row + 8) * DD + col)
                = make_float2(acc[mt][j][2], acc[mt][j][3]);
        }
    }

    // Fused per-batch column sums (V GEMM only)
    if (A.vsum) {
        int b = bm / SS;
        #pragma unroll
        for (int j = 0; j < NJ; j++) {
            float s0 = 0.0f, s1 = 0.0f;
            #pragma unroll
            for (int mt = 0; mt < 4; mt++) {
                s0 += acc[mt][j][0] + acc[mt][j][2];
                s1 += acc[mt][j][1] + acc[mt][j][3];
            }
            #pragma unroll
            for (int o = 4; o < 32; o <<= 1) {
                s0 += __shfl_xor_sync(0xFFFFFFFFu, s0, o);
                s1 += __shfl_xor_sync(0xFFFFFFFFu, s1, o);
            }
            if (lane < 4) {
                int col = bn + wn + j * 8 + lane * 2;
                atomicAdd(&A.vsum[b * DD + col], s0);
                atomicAdd(&A.vsum[b * DD + col + 1], s1);
            }
        }
    }
}

// ---------------------------------------------------------------------------
// fp32 -> (f16 hi, f16 lo) splits; lo pointer may be null
// ---------------------------------------------------------------------------
__device__ __forceinline__ void split4h(float4 v, ushort4& h, ushort4& l) {
    __half b;
    b = __float2half(v.x); h.x = __half_as_ushort(b);
    l.x = __half_as_ushort(__float2half(v.x - __half2float(b)));
    b = __float2half(v.y); h.y = __half_as_ushort(b);
    l.y = __half_as_ushort(__float2half(v.y - __half2float(b)));
    b = __float2half(v.z); h.z = __half_as_ushort(b);
    l.z = __half_as_ushort(__float2half(v.z - __half2float(b)));
    b = __float2half(v.w); h.w = __half_as_ushort(b);
    l.w = __half_as_ushort(__float2half(v.w - __half2float(b)));
}

struct SplitN {
    const float4* x[4];
    ushort4* hi[4];
    ushort4* lo[4];
};
__global__ void split_multi(SplitN a, int n4)
{
    int w = blockIdx.y;
    int i = blockIdx.x * blockDim.x + threadIdx.x;
    if (i >= n4) return;
    ushort4 h, l;
    split4h(a.x[w][i], h, l);
    a.hi[w][i] = h;
    if (a.lo[w]) a.lo[w][i] = l;
}

__global__ void zero_vsum() {
    int i = blockIdx.x * blockDim.x + threadIdx.x;
    if (i < BB * DD) g_vsum[i] = 0.0f;
}

// ---------------------------------------------------------------------------
// Middle rows; writes f16 hi/lo directly (fused split for the O GEMM).
// ---------------------------------------------------------------------------
__device__ __forceinline__ void store_hl(size_t off, float v) {
    __half h = __float2half(v);
    g_ah[off] = h;
    g_al[off] = __float2half(v - __half2float(h));
}

__global__ void mid_kernel(const int* __restrict__ idx)
{
    const int warps_per_block = 8;
    int item = blockIdx.x * warps_per_block + (threadIdx.x >> 5);
    const int n_items = BB * NH * SMID;
    if (item >= n_items) return;
    int lane = threadIdx.x & 31;

    int i = item % SMID;
    int h = (item / SMID) % NH;
    int b = item / (SMID * NH);
    int s = i + GG;

    const float* qrow = g_q + ((size_t)b * SS + s) * DD + h * DK;
    float q0 = qrow[lane];
    float q1 = qrow[lane + 32];

    int cols[NIDX];
    #pragma unroll
    for (int j = 0; j < NIDX; j++) cols[j] = idx[i * NIDX + j];

    float k0v[NIDX], k1v[NIDX];
    #pragma unroll
    for (int j = 0; j < NIDX; j++) {
        const float* krow = g_k + ((size_t)b * SS + cols[j]) * DD + h * DK;
        k0v[j] = krow[lane];
        k1v[j] = krow[lane + 32];
    }

    float sc[NIDX];
    #pragma unroll
    for (int j = 0; j < NIDX; j++) {
        float p = q0 * k0v[j] + q1 * k1v[j];
        #pragma unroll
        for (int o = 16; o > 0; o >>= 1) p += __shfl_xor_sync(0xFFFFFFFFu, p, o);
        sc[j] = p;
    }

    float wgt[NIDX];
    float denom = (float)SS;
    #pragma unroll
    for (int j = 0; j < NIDX; j++) {
        bool dup = false;
        #pragma unroll
        for (int jj = 0; jj < NIDX; jj++)
            if (jj < j) dup = dup || (cols[jj] == cols[j]);
        float w = dup ? 0.0f : (expf(sc[j] * 0.125f) - 1.0f);
        wgt[j] = w;
        denom += w;
    }

    const float* vs = g_vsum + b * DD + h * DV;
    float o0 = vs[lane];
    float o1 = vs[lane + 32];
    #pragma unroll
    for (int j = 0; j < NIDX; j++) {
        const float* vrow = g_v + ((size_t)b * SS + cols[j]) * DD + h * DV;
        o0 = fmaf(wgt[j], vrow[lane], o0);
        o1 = fmaf(wgt[j], vrow[lane + 32], o1);
    }
    float inv = 1.0f / denom;
    size_t base = ((size_t)b * SS + s) * DD + h * DV;
    store_hl(base + lane, o0 * inv);
    store_hl(base + lane + 32, o1 * inv);
}

// ---------------------------------------------------------------------------
// Global rows (s=0, s=2047): full softmax over all 2048 keys.
// ---------------------------------------------------------------------------
__global__ void global_kernel()
{
    int item = blockIdx.x;
    int r = item % 2;
    int h = (item / 2) % NH;
    int b = item / (2 * NH);
    int s = r ? (SS - 1) : 0;
    int tid = threadIdx.x;

    __shared__ float sc[SS];
    __shared__ float qs[DK];
    __shared__ float red[256];

    const float* qrow = g_q + ((size_t)b * SS + s) * DD + h * DK;
    if (tid < DK) qs[tid] = qrow[tid];
    __syncthreads();

    for (int t = tid; t < SS; t += 256) {
        const float* krow = g_k + ((size_t)b * SS + t) * DD + h * DK;
        float p = 0.0f;
        #pragma unroll
        for (int d = 0; d < DK; d++) p = fmaf(qs[d], krow[d], p);
        sc[t] = p * 0.125f;
    }
    __syncthreads();

    float m = -1e30f;
    for (int t = tid; t < SS; t += 256) m = fmaxf(m, sc[t]);
    red[tid] = m; __syncthreads();
    for (int o = 128; o > 0; o >>= 1) {
        if (tid < o) red[tid] = fmaxf(red[tid], red[tid + o]);
        __syncthreads();
    }
    m = red[0];
    __syncthreads();

    float sum = 0.0f;
    for (int t = tid; t < SS; t += 256) {
        float e = expf(sc[t] - m);
        sc[t] = e;
        sum += e;
    }
    red[tid] = sum; __syncthreads();
    for (int o = 128; o > 0; o >>= 1) {
        if (tid < o) red[tid] += red[tid + o];
        __syncthreads();
    }
    float inv = 1.0f / red[0];
    __syncthreads();

    int dv = tid % DV;
    int chunk = tid / DV;
    float acc = 0.0f;
    const float* vb = g_v + (size_t)b * SS * DD + h * DV + dv;
    for (int t = chunk * (SS / 4); t < (chunk + 1) * (SS / 4); t++)
        acc = fmaf(sc[t], vb[(size_t)t * DD], acc);
    red[tid] = acc; __syncthreads();
    if (tid < DV) {
        float o = (red[dv] + red[DV + dv] + red[2 * DV + dv] + red[3 * DV + dv]) * inv;
        store_hl(((size_t)b * SS + s) * DD + h * DV + dv, o);
    }
}

// ---------------------------------------------------------------------------
extern "C" void kernel_launch(void* const* d_in, const int* in_sizes, int n_in,
                              void* d_out, int out_size)
{
    const float* Q  = (const float*)d_in[0];
    const float* K  = (const float*)d_in[1];
    const float* V  = (const float*)d_in[2];
    const float* Wq = (const float*)d_in[3];
    const float* Wk = (const float*)d_in[4];
    const float* Wv = (const float*)d_in[5];
    const float* Wo = (const float*)d_in[6];
    const int*   idx = (const int*)d_in[7];
    float* out = (float*)d_out;

    float *pq, *pk, *pv, *pvs;
    cudaGetSymbolAddress((void**)&pq, g_q);
    cudaGetSymbolAddress((void**)&pk, g_k);
    cudaGetSymbolAddress((void**)&pv, g_v);
    cudaGetSymbolAddress((void**)&pvs, g_vsum);

    __half *qh, *kh, *vh, *vl, *ah, *al;
    __half *wqh, *wql, *wkh, *wkl, *wvh, *wvl, *woh, *wol;
    cudaGetSymbolAddress((void**)&qh, g_qh);
    cudaGetSymbolAddress((void**)&kh, g_kh);
    cudaGetSymbolAddress((void**)&vh, g_vh);  cudaGetSymbolAddress((void**)&vl, g_vl);
    cudaGetSymbolAddress((void**)&ah, g_ah);  cudaGetSymbolAddress((void**)&al, g_al);
    cudaGetSymbolAddress((void**)&wqh, g_wqh); cudaGetSymbolAddress((void**)&wql, g_wql);
    cudaGetSymbolAddress((void**)&wkh, g_wkh); cudaGetSymbolAddress((void**)&wkl, g_wkl);
    cudaGetSymbolAddress((void**)&wvh, g_wvh); cudaGetSymbolAddress((void**)&wvl, g_wvl);
    cudaGetSymbolAddress((void**)&woh, g_woh); cudaGetSymbolAddress((void**)&wol, g_wol);

    constexpr int SMEM128 = NSTG * (2 * 128 * LDT * 2 + 2 * 128 * LDT * 2); // 81920
    constexpr int SMEM64  = NSTG * (2 * 128 * LDT * 2 + 2 * 64 * LDT * 2);  // 61440
    cudaFuncSetAttribute(gemm_mma<128>, cudaFuncAttributeMaxDynamicSharedMemorySize, SMEM128);
    cudaFuncSetAttribute(gemm_mma<64>,  cudaFuncAttributeMaxDynamicSharedMemorySize, SMEM64);

    const int n4_big = MROWS * DD / 4;
    const int n4_w   = DD * DD / 4;
    const int bl_big = (n4_big + 255) / 256;
    const int bl_w   = (n4_w + 255) / 256;

    zero_vsum<<<6, 256>>>();

    SplitN si;
    si.x[0] = (const float4*)Q; si.hi[0] = (ushort4*)qh; si.lo[0] = nullptr;
    si.x[1] = (const float4*)K; si.hi[1] = (ushort4*)kh; si.lo[1] = nullptr;
    si.x[2] = (const float4*)V; si.hi[2] = (ushort4*)vh; si.lo[2] = (ushort4*)vl;
    si.x[3] = si.x[0]; si.hi[3] = si.hi[0]; si.lo[3] = nullptr;
    split_multi<<<dim3(bl_big, 3), 256>>>(si, n4_big);

    SplitN sw;
    sw.x[0] = (const float4*)Wq; sw.hi[0] = (ushort4*)wqh; sw.lo[0] = (ushort4*)wql;
    sw.x[1] = (const float4*)Wk; sw.hi[1] = (ushort4*)wkh; sw.lo[1] = (ushort4*)wkl;
    sw.x[2] = (const float4*)Wv; sw.hi[2] = (ushort4*)wvh; sw.lo[2] = (ushort4*)wvl;
    sw.x[3] = (const float4*)Wo; sw.hi[3] = (ushort4*)woh; sw.lo[3] = (ushort4*)wol;
    split_multi<<<dim3(bl_w, 4), 256>>>(sw, n4_w);

    Gemm3 g3;
    g3.g[0] = {qh, nullptr, wqh, wql, pq, nullptr, 0};
    g3.g[1] = {kh, nullptr, wkh, wkl, pk, nullptr, 0};
    g3.g[2] = {vh, vl,      wvh, wvl, pv, pvs,     1};
    gemm_mma<128><<<dim3(DD / 128, MROWS / BM, 3), 256, SMEM128>>>(g3);

    const int n_items = BB * NH * SMID;
    mid_kernel<<<(n_items + 7) / 8, 256>>>(idx);
    global_kernel<<<BB * NH * 2, 256>>>();

    Gemm3 go;
    go.g[0] = {ah, al, woh, wol, out, nullptr, 1};
    go.g[1] = go.g[0];
    go.g[2] = go.g[0];
    gemm_mma<64><<<dim3(DD / 64, MROWS / BM, 1), 256, SMEM64>>>(go);
}

// round 8
// speedup vs baseline: 1.1962x; 1.0444x over previous
#include <cuda_runtime.h>
#include <cuda_fp16.h>
#include <cstdint>
#include <math.h>

// Problem constants
#define BB 2
#define SS 2048
#define DD 768
#define NH 12
#define DK 64
#define DV 64
#define GG 1
#define NIDX 6
#define SMID (SS - 2*GG)
#define MROWS (BB * SS)

// GEMM tiling
#define BM 128
#define BKK 32                    // f16 K elems per stage
#define NCHK (DD / BKK)           // 24 k-iterations
#define LDT 40                    // padded row stride (elements): 80B
#define NSTG 2

// ---------------------------------------------------------------------------
// Scratch
// ---------------------------------------------------------------------------
__device__ float g_v[MROWS * DD];
__device__ float g_vsum[BB * DD];

__device__ __half g_qp[MROWS * DD];          // projected q (f16)
__device__ __half g_kp[MROWS * DD];          // projected k (f16)
__device__ __half g_qh[MROWS * DD];          // input Q hi
__device__ __half g_kh[MROWS * DD];          // input K hi
__device__ __half g_vh[MROWS * DD], g_vl[MROWS * DD];
__device__ __half g_ah[MROWS * DD], g_al[MROWS * DD];
__device__ __half g_wqh[DD * DD];
__device__ __half g_wkh[DD * DD];
__device__ __half g_wvh[DD * DD], g_wvl[DD * DD];
__device__ __half g_woh[DD * DD], g_wol[DD * DD];

// ---------------------------------------------------------------------------
// PTX helpers (portable sm_80+ ISA)
// ---------------------------------------------------------------------------
__device__ __forceinline__ uint32_t smem_u32(const void* p) {
    uint32_t a;
    asm("{ .reg .u64 t; cvta.to.shared.u64 t, %1; cvt.u32.u64 %0, t; }"
        : "=r"(a) : "l"(p));
    return a;
}
__device__ __forceinline__ void cp_async16(uint32_t dst, const void* src) {
    asm volatile("cp.async.cg.shared.global [%0], [%1], 16;"
                 :: "r"(dst), "l"(src) : "memory");
}
__device__ __forceinline__ void cp_commit() {
    asm volatile("cp.async.commit_group;" ::: "memory");
}
template <int N>
__device__ __forceinline__ void cp_wait() {
    asm volatile("cp.async.wait_group %0;" :: "n"(N) : "memory");
}
__device__ __forceinline__ void ldm4(uint32_t* r, uint32_t addr) {
    asm volatile("ldmatrix.sync.aligned.m8n8.x4.shared.b16 {%0,%1,%2,%3}, [%4];"
                 : "=r"(r[0]), "=r"(r[1]), "=r"(r[2]), "=r"(r[3]) : "r"(addr));
}
__device__ __forceinline__ void mma16816(float* c, const uint32_t* a, const uint32_t* b) {
    asm volatile(
        "mma.sync.aligned.m16n8k16.row.col.f32.f16.f16.f32 "
        "{%0,%1,%2,%3}, {%4,%5,%6,%7}, {%8,%9}, {%0,%1,%2,%3};"
        : "+f"(c[0]), "+f"(c[1]), "+f"(c[2]), "+f"(c[3])
        : "r"(a[0]), "r"(a[1]), "r"(a[2]), "r"(a[3]), "r"(b[0]), "r"(b[1]));
}

struct GemmArgs {
    const __half *Ah, *Al, *Bh, *Bl;
    float* C;         // fp32 output (used when Ch == nullptr)
    __half* Ch;       // f16 output (q/k projections)
    float* vsum;      // non-null: accumulate per-batch column sums (V GEMM)
    int nprod;        // 1: Ah*Bh ; 3: Ah*Bh + Ah*Bl + Al*Bh
};
struct Gemm3 { GemmArgs g[3]; };

// ---------------------------------------------------------------------------
// C[M,768] = Ah*Bh^T (+ Ah*Bl^T + Al*Bh^T)   f16 split-fp32, B is [768,768]
// Template on BNT (CTA N-tile). 8 warps, 2m x 4n layout, NSTG=2, 2 CTAs/SM.
// ---------------------------------------------------------------------------
template <int BNT>
__global__ __launch_bounds__(256, 2) void gemm_mma(Gemm3 ga)
{
    constexpr int WNT = BNT / 4;                 // warp n-tile (32 or 16)
    constexpr int NJ = WNT / 8;                  // n8 tiles per warp (4 or 2)
    constexpr int TILEB_A = 128 * LDT * 2;       // 10240
    constexpr int TILEB_B = BNT * LDT * 2;
    constexpr int STAGEB = 2 * TILEB_A + 2 * TILEB_B;
    constexpr int NCHUNK = (2 * 128 + 2 * BNT) * 4;   // 16B chunks per stage
    constexpr int PER_THR = NCHUNK / 256;

    extern __shared__ char smem[];
    const GemmArgs& A = ga.g[blockIdx.z];
    const int nprod = A.nprod;
    const uint32_t sb = smem_u32(smem);
    const int tid = threadIdx.x;
    const int wid = tid >> 5;
    const int lane = tid & 31;
    const int bm = blockIdx.y * BM;
    const int bn = blockIdx.x * BNT;
    const int wm = (wid >> 2) * 64;
    const int wn = (wid & 3) * WNT;

    float acc[4][NJ][4];
    #pragma unroll
    for (int i = 0; i < 4; i++)
        #pragma unroll
        for (int j = 0; j < NJ; j++)
            #pragma unroll
            for (int e = 0; e < 4; e++) acc[i][j][e] = 0.0f;

    // chunk layout: [Ah(512) | Al(512) | Bh(BNT*4) | Bl(BNT*4)]
    auto issue = [&](int kt) {
        const int st = kt % NSTG;
        #pragma unroll
        for (int q8 = 0; q8 < PER_THR; q8++) {
            int q = tid + q8 * 256;
            if (q < 1024) {
                int t = q >> 9;                  // 0=Ah 1=Al
                if (t == 1 && nprod < 3) continue;
                int r = (q >> 2) & 127;
                int c = q & 3;
                const __half* src = (t ? A.Al : A.Ah)
                                    + (size_t)(bm + r) * DD + kt * BKK + c * 8;
                uint32_t dst = sb + st * STAGEB + t * TILEB_A + r * (LDT * 2) + c * 16;
                cp_async16(dst, src);
            } else {
                int q2 = q - 1024;
                int t = q2 / (BNT * 4);          // 0=Bh 1=Bl
                if (t == 1 && nprod < 2) continue;
                int r = (q2 >> 2) % BNT;
                int c = q2 & 3;
                const __half* src = (t ? A.Bl : A.Bh)
                                    + (size_t)(bn + r) * DD + kt * BKK + c * 8;
                uint32_t dst = sb + st * STAGEB + 2 * TILEB_A + t * TILEB_B
                             + r * (LDT * 2) + c * 16;
                cp_async16(dst, src);
            }
        }
        cp_commit();
    };

    const int a_row = lane & 15;
    const int a_col = (lane >> 4) * 8;
    const int b_row = (lane & 7) + ((lane >> 4) << 3);
    const int b_col = ((lane >> 3) & 1) * 8;

    auto compute = [&](int kt) {
        const uint32_t base = sb + (kt % NSTG) * STAGEB;
        #pragma unroll
        for (int ks = 0; ks < 2; ks++) {
            const int k0 = ks * 16;
            uint32_t bh[NJ / 2][4], bl[NJ / 2][4];
            #pragma unroll
            for (int nh = 0; nh < NJ / 2; nh++) {
                uint32_t off = (uint32_t)(wn + nh * 16 + b_row) * (LDT * 2)
                             + (k0 + b_col) * 2;
                ldm4(bh[nh], base + 2 * TILEB_A + off);
                if (nprod >= 2)
                    ldm4(bl[nh], base + 2 * TILEB_A + TILEB_B + off);
            }
            uint32_t af[4][4];
            #pragma unroll
            for (int mt = 0; mt < 4; mt++) {
                uint32_t off = (uint32_t)(wm + mt * 16 + a_row) * (LDT * 2)
                             + (k0 + a_col) * 2;
                ldm4(af[mt], base + off);
            }
            #pragma unroll
            for (int mt = 0; mt < 4; mt++)
                #pragma unroll
                for (int j = 0; j < NJ; j++) {
                    mma16816(acc[mt][j], af[mt], &bh[j >> 1][(j & 1) * 2]);
                    if (nprod >= 2)
                        mma16816(acc[mt][j], af[mt], &bl[j >> 1][(j & 1) * 2]);
                }
            if (nprod >= 3) {   // third product: Al * Bh
                #pragma unroll
                for (int mt = 0; mt < 4; mt++) {
                    uint32_t off = (uint32_t)(wm + mt * 16 + a_row) * (LDT * 2)
                                 + (k0 + a_col) * 2;
                    ldm4(af[mt], base + TILEB_A + off);
                }
                #pragma unroll
                for (int mt = 0; mt < 4; mt++)
                    #pragma unroll
                    for (int j = 0; j < NJ; j++)
                        mma16816(acc[mt][j], af[mt], &bh[j >> 1][(j & 1) * 2]);
            }
        }
    };

    issue(0);
    for (int kt = 0; kt < NCHK; kt++) {
        cp_wait<0>();
        __syncthreads();
        if (kt + 1 < NCHK) issue(kt + 1);
        compute(kt);
    }

    if (A.Ch) {   // f16 output (q/k projections)
        #pragma unroll
        for (int mt = 0; mt < 4; mt++) {
            #pragma unroll
            for (int j = 0; j < NJ; j++) {
                int row = bm + wm + mt * 16 + (lane >> 2);
                int col = bn + wn + j * 8 + (lane & 3) * 2;
                *reinterpret_cast<__half2*>(A.Ch + (size_t)row * DD + col)
                    = __floats2half2_rn(acc[mt][j][0], acc[mt][j][1]);
                *reinterpret_cast<__half2*>(A.Ch + (size_t)(row + 8) * DD + col)
                    = __floats2half2_rn(acc[mt][j][2], acc[mt][j][3]);
            }
        }
    } else {
        #pragma unroll
        for (int mt = 0; mt < 4; mt++) {
            #pragma unroll
            for (int j = 0; j < NJ; j++) {
                int row = bm + wm + mt * 16 + (lane >> 2);
                int col = bn + wn + j * 8 + (lane & 3) * 2;
                *reinterpret_cast<float2*>(A.C + (size_t)row * DD + col)
                    = make_float2(acc[mt][j][0], acc[mt][j][1]);
                *reinterpret_cast<float2*>(A.C + (size_t)(row + 8) * DD + col)
                    = make_float2(acc[mt][j][2], acc[mt][j][3]);
            }
        }
    }

    // Fused per-batch column sums (V GEMM only)
    if (A.vsum) {
        int b = bm / SS;
        #pragma unroll
        for (int j = 0; j < NJ; j++) {
            float s0 = 0.0f, s1 = 0.0f;
            #pragma unroll
            for (int mt = 0; mt < 4; mt++) {
                s0 += acc[mt][j][0] + acc[mt][j][2];
                s1 += acc[mt][j][1] + acc[mt][j][3];
            }
            #pragma unroll
            for (int o = 4; o < 32; o <<= 1) {
                s0 += __shfl_xor_sync(0xFFFFFFFFu, s0, o);
                s1 += __shfl_xor_sync(0xFFFFFFFFu, s1, o);
            }
            if (lane < 4) {
                int col = bn + wn + j * 8 + lane * 2;
                atomicAdd(&A.vsum[b * DD + col], s0);
                atomicAdd(&A.vsum[b * DD + col + 1], s1);
            }
        }
    }
}

// ---------------------------------------------------------------------------
// fp32 -> (f16 hi, f16 lo) splits; lo pointer may be null
// ---------------------------------------------------------------------------
__device__ __forceinline__ void split4h(float4 v, ushort4& h, ushort4& l) {
    __half b;
    b = __float2half(v.x); h.x = __half_as_ushort(b);
    l.x = __half_as_ushort(__float2half(v.x - __half2float(b)));
    b = __float2half(v.y); h.y = __half_as_ushort(b);
    l.y = __half_as_ushort(__float2half(v.y - __half2float(b)));
    b = __float2half(v.z); h.z = __half_as_ushort(b);
    l.z = __half_as_ushort(__float2half(v.z - __half2float(b)));
    b = __float2half(v.w); h.w = __half_as_ushort(b);
    l.w = __half_as_ushort(__float2half(v.w - __half2float(b)));
}

struct SplitN {
    const float4* x[4];
    ushort4* hi[4];
    ushort4* lo[4];
};
__global__ void split_multi(SplitN a, int n4)
{
    int w = blockIdx.y;
    int i = blockIdx.x * blockDim.x + threadIdx.x;
    if (i >= n4) return;
    ushort4 h, l;
    split4h(a.x[w][i], h, l);
    a.hi[w][i] = h;
    if (a.lo[w]) a.lo[w][i] = l;
}

__global__ void zero_vsum() {
    int i = blockIdx.x * blockDim.x + threadIdx.x;
    if (i < BB * DD) g_vsum[i] = 0.0f;
}

// ---------------------------------------------------------------------------
// Middle rows; q/k read as f16, v fp32; writes f16 hi/lo (for the O GEMM).
// ---------------------------------------------------------------------------
__device__ __forceinline__ void store_hl(size_t off, float v) {
    __half h = __float2half(v);
    g_ah[off] = h;
    g_al[off] = __float2half(v - __half2float(h));
}

__global__ void mid_kernel(const int* __restrict__ idx)
{
    const int warps_per_block = 8;
    int item = blockIdx.x * warps_per_block + (threadIdx.x >> 5);
    const int n_items = BB * NH * SMID;
    if (item >= n_items) return;
    int lane = threadIdx.x & 31;

    int i = item % SMID;
    int h = (item / SMID) % NH;
    int b = item / (SMID * NH);
    int s = i + GG;

    const __half* qrow = g_qp + ((size_t)b * SS + s) * DD + h * DK;
    float q0 = __half2float(qrow[lane]);
    float q1 = __half2float(qrow[lane + 32]);

    int cols[NIDX];
    #pragma unroll
    for (int j = 0; j < NIDX; j++) cols[j] = idx[i * NIDX + j];

    float k0v[NIDX], k1v[NIDX];
    #pragma unroll
    for (int j = 0; j < NIDX; j++) {
        const __half* krow = g_kp + ((size_t)b * SS + cols[j]) * DD + h * DK;
        k0v[j] = __half2float(krow[lane]);
        k1v[j] = __half2float(krow[lane + 32]);
    }

    float sc[NIDX];
    #pragma unroll
    for (int j = 0; j < NIDX; j++) {
        float p = q0 * k0v[j] + q1 * k1v[j];
        #pragma unroll
        for (int o = 16; o > 0; o >>= 1) p += __shfl_xor_sync(0xFFFFFFFFu, p, o);
        sc[j] = p;
    }

    float wgt[NIDX];
    float denom = (float)SS;
    #pragma unroll
    for (int j = 0; j < NIDX; j++) {
        bool dup = false;
        #pragma unroll
        for (int jj = 0; jj < NIDX; jj++)
            if (jj < j) dup = dup || (cols[jj] == cols[j]);
        float w = dup ? 0.0f : (expf(sc[j] * 0.125f) - 1.0f);
        wgt[j] = w;
        denom += w;
    }

    const float* vs = g_vsum + b * DD + h * DV;
    float o0 = vs[lane];
    float o1 = vs[lane + 32];
    #pragma unroll
    for (int j = 0; j < NIDX; j++) {
        const float* vrow = g_v + ((size_t)b * SS + cols[j]) * DD + h * DV;
        o0 = fmaf(wgt[j], vrow[lane], o0);
        o1 = fmaf(wgt[j], vrow[lane + 32], o1);
    }
    float inv = 1.0f / denom;
    size_t base = ((size_t)b * SS + s) * DD + h * DV;
    store_hl(base + lane, o0 * inv);
    store_hl(base + lane + 32, o1 * inv);
}

// ---------------------------------------------------------------------------
// Global rows (s=0, s=2047): full softmax over all 2048 keys.
// ---------------------------------------------------------------------------
__global__ void global_kernel()
{
    int item = blockIdx.x;
    int r = item % 2;
    int h = (item / 2) % NH;
    int b = item / (2 * NH);
    int s = r ? (SS - 1) : 0;
    int tid = threadIdx.x;

    __shared__ float sc[SS];
    __shared__ float qs[DK];
    __shared__ float red[256];

    const __half* qrow = g_qp + ((size_t)b * SS + s) * DD + h * DK;
    if (tid < DK) qs[tid] = __half2float(qrow[tid]);
    __syncthreads();

    for (int t = tid; t < SS; t += 256) {
        const __half* krow = g_kp + ((size_t)b * SS + t) * DD + h * DK;
        float p = 0.0f;
        #pragma unroll
        for (int d = 0; d < DK; d++) p = fmaf(qs[d], __half2float(krow[d]), p);
        sc[t] = p * 0.125f;
    }
    __syncthreads();

    float m = -1e30f;
    for (int t = tid; t < SS; t += 256) m = fmaxf(m, sc[t]);
    red[tid] = m; __syncthreads();
    for (int o = 128; o > 0; o >>= 1) {
        if (tid < o) red[tid] = fmaxf(red[tid], red[tid + o]);
        __syncthreads();
    }
    m = red[0];
    __syncthreads();

    float sum = 0.0f;
    for (int t = tid; t < SS; t += 256) {
        float e = expf(sc[t] - m);
        sc[t] = e;
        sum += e;
    }
    red[tid] = sum; __syncthreads();
    for (int o = 128; o > 0; o >>= 1) {
        if (tid < o) red[tid] += red[tid + o];
        __syncthreads();
    }
    float inv = 1.0f / red[0];
    __syncthreads();

    int dv = tid % DV;
    int chunk = tid / DV;
    float acc = 0.0f;
    const float* vb = g_v + (size_t)b * SS * DD + h * DV + dv;
    for (int t = chunk * (SS / 4); t < (chunk + 1) * (SS / 4); t++)
        acc = fmaf(sc[t], vb[(size_t)t * DD], acc);
    red[tid] = acc; __syncthreads();
    if (tid < DV) {
        float o = (red[dv] + red[DV + dv] + red[2 * DV + dv] + red[3 * DV + dv]) * inv;
        store_hl(((size_t)b * SS + s) * DD + h * DV + dv, o);
    }
}

// ---------------------------------------------------------------------------
extern "C" void kernel_launch(void* const* d_in, const int* in_sizes, int n_in,
                              void* d_out, int out_size)
{
    const float* Q  = (const float*)d_in[0];
    const float* K  = (const float*)d_in[1];
    const float* V  = (const float*)d_in[2];
    const float* Wq = (const float*)d_in[3];
    const float* Wk = (const float*)d_in[4];
    const float* Wv = (const float*)d_in[5];
    const float* Wo = (const float*)d_in[6];
    const int*   idx = (const int*)d_in[7];
    float* out = (float*)d_out;

    float *pv, *pvs;
    cudaGetSymbolAddress((void**)&pv, g_v);
    cudaGetSymbolAddress((void**)&pvs, g_vsum);

    __half *qp, *kp, *qh, *kh, *vh, *vl, *ah, *al;
    __half *wqh, *wkh, *wvh, *wvl, *woh, *wol;
    cudaGetSymbolAddress((void**)&qp, g_qp);
    cudaGetSymbolAddress((void**)&kp, g_kp);
    cudaGetSymbolAddress((void**)&qh, g_qh);
    cudaGetSymbolAddress((void**)&kh, g_kh);
    cudaGetSymbolAddress((void**)&vh, g_vh);  cudaGetSymbolAddress((void**)&vl, g_vl);
    cudaGetSymbolAddress((void**)&ah, g_ah);  cudaGetSymbolAddress((void**)&al, g_al);
    cudaGetSymbolAddress((void**)&wqh, g_wqh);
    cudaGetSymbolAddress((void**)&wkh, g_wkh);
    cudaGetSymbolAddress((void**)&wvh, g_wvh); cudaGetSymbolAddress((void**)&wvl, g_wvl);
    cudaGetSymbolAddress((void**)&woh, g_woh); cudaGetSymbolAddress((void**)&wol, g_wol);

    constexpr int SMEM128 = NSTG * (2 * 128 * LDT * 2 + 2 * 128 * LDT * 2); // 81920
    constexpr int SMEM64  = NSTG * (2 * 128 * LDT * 2 + 2 * 64 * LDT * 2);  // 61440
    cudaFuncSetAttribute(gemm_mma<128>, cudaFuncAttributeMaxDynamicSharedMemorySize, SMEM128);
    cudaFuncSetAttribute(gemm_mma<64>,  cudaFuncAttributeMaxDynamicSharedMemorySize, SMEM64);

    const int n4_big = MROWS * DD / 4;
    const int n4_w   = DD * DD / 4;
    const int bl_big = (n4_big + 255) / 256;
    const int bl_w   = (n4_w + 255) / 256;

    zero_vsum<<<6, 256>>>();

    SplitN si;
    si.x[0] = (const float4*)Q; si.hi[0] = (ushort4*)qh; si.lo[0] = nullptr;
    si.x[1] = (const float4*)K; si.hi[1] = (ushort4*)kh; si.lo[1] = nullptr;
    si.x[2] = (const float4*)V; si.hi[2] = (ushort4*)vh; si.lo[2] = (ushort4*)vl;
    si.x[3] = si.x[0]; si.hi[3] = si.hi[0]; si.lo[3] = nullptr;
    split_multi<<<dim3(bl_big, 3), 256>>>(si, n4_big);

    SplitN sw;
    sw.x[0] = (const float4*)Wq; sw.hi[0] = (ushort4*)wqh; sw.lo[0] = nullptr;
    sw.x[1] = (const float4*)Wk; sw.hi[1] = (ushort4*)wkh; sw.lo[1] = nullptr;
    sw.x[2] = (const float4*)Wv; sw.hi[2] = (ushort4*)wvh; sw.lo[2] = (ushort4*)wvl;
    sw.x[3] = (const float4*)Wo; sw.hi[3] = (ushort4*)woh; sw.lo[3] = (ushort4*)wol;
    split_multi<<<dim3(bl_w, 4), 256>>>(sw, n4_w);

    Gemm3 g3;
    g3.g[0] = {qh, nullptr, wqh, nullptr, nullptr, qp, nullptr, 1};
    g3.g[1] = {kh, nullptr, wkh, nullptr, nullptr, kp, nullptr, 1};
    g3.g[2] = {vh, vl,      wvh, wvl,     pv,      nullptr, pvs, 3};
    gemm_mma<128><<<dim3(DD / 128, MROWS / BM, 3), 256, SMEM128>>>(g3);

    const int n_items = BB * NH * SMID;
    mid_kernel<<<(n_items + 7) / 8, 256>>>(idx);
    global_kernel<<<BB * NH * 2, 256>>>();

    Gemm3 go;
    go.g[0] = {ah, al, woh, wol, out, nullptr, nullptr, 3};
    go.g[1] = go.g[0];
    go.g[2] = go.g[0];
    gemm_mma<64><<<dim3(DD / 64, MROWS / BM, 1), 256, SMEM64>>>(go);
}